// round 3
// baseline (speedup 1.0000x reference)
#include <cuda_runtime.h>
#include <math.h>

// ---------------- problem constants ----------------
#define SLOTS      85         // 81 classes + 4 box coords
#define TILE_A     64         // anchors per block tile
#define TILE_F     (TILE_A * SLOTS)       // 5440 floats per array per tile
#define NBINS      3072
#define HIST_LO   (-8.0f)
#define HIST_INVW (192.0f)    // NBINS / 16
#define NBLOCKS    444        // 3 per SM

// ---------------- device scratch ----------------
__device__ int    g_npos;
__device__ double g_pos_loss;
__device__ double g_loc_loss;
__device__ int    g_hist_cnt[NBINS];
__device__ float  g_hist_sum[NBINS];

// ---------------- K0: zero scratch ----------------
__global__ void ssd_init_kernel() {
    int i = blockIdx.x * blockDim.x + threadIdx.x;
    if (i < NBINS) { g_hist_cnt[i] = 0; g_hist_sum[i] = 0.0f; }
    if (i == 0) { g_npos = 0; g_pos_loss = 0.0; g_loc_loss = 0.0; }
}

// ---------------- K1: smem-staged streaming pass ----------------
// Per tile: stage 64 anchors (yt+yp) with float4 coalesced loads, then
// 4 threads per anchor consume 21/22 contiguous slots each from smem.
__global__ __launch_bounds__(256) void ssd_main_kernel(
    const float* __restrict__ yp,
    const float* __restrict__ yt,
    int nanch)
{
    extern __shared__ float smem[];
    float* s_yt = smem;                       // TILE_F floats
    float* s_yp = smem + TILE_F;              // TILE_F floats
    int*   s_cnt = (int*)(smem + 2 * TILE_F); // NBINS ints
    float* s_sum = (float*)(s_cnt + NBINS);   // NBINS floats

    const int tid = threadIdx.x;
    for (int i = tid; i < NBINS; i += 256) { s_cnt[i] = 0; s_sum[i] = 0.0f; }

    const int a  = tid >> 2;          // anchor within tile (0..63)
    const int q  = tid & 3;           // quarter of the slot row
    const int sbeg = q * 21;          // q: 0..2 -> 21 slots, q==3 -> 22 slots
    const int scnt = (q == 3) ? 22 : 21;

    float accPos = 0.0f, accLoc = 0.0f;
    int   accN = 0;

    const int ntiles = (nanch + TILE_A - 1) / TILE_A;

    for (int tile = blockIdx.x; tile < ntiles; tile += NBLOCKS) {
        const long long abase = (long long)tile * TILE_A;
        const int valid = (int)min((long long)TILE_A, (long long)nanch - abase);
        const size_t fbase = (size_t)abase * SLOTS;
        const int nfl  = valid * SLOTS;
        const int nfl4 = nfl >> 2;

        __syncthreads();   // previous compute done before overwriting buffers

        // ---- stage: coalesced float4 loads ----
        const float4* gt4 = (const float4*)(yt + fbase);
        const float4* gp4 = (const float4*)(yp + fbase);
        float4* st4 = (float4*)s_yt;
        float4* sp4 = (float4*)s_yp;
        for (int i = tid; i < nfl4; i += 256) st4[i] = gt4[i];
        for (int i = tid; i < nfl4; i += 256) sp4[i] = gp4[i];
        for (int i = (nfl4 << 2) + tid; i < nfl; i += 256) {  // scalar tail (rare)
            s_yt[i] = yt[fbase + i];
            s_yp[i] = yp[fbase + i];
        }
        __syncthreads();

        // ---- compute: 4 threads per anchor ----
        float c = 0.0f, sl = 0.0f, tsum = 0.0f, t00 = 0.0f;
        if (a < valid) {
            const float* rt = s_yt + a * SLOTS;
            const float* rp = s_yp + a * SLOTS;
            #pragma unroll
            for (int k = 0; k < 22; k++) {
                if (k >= scnt) break;
                int s = sbeg + k;
                float t = rt[s];
                float p = rp[s];
                if (s < 81) {
                    c = fmaf(t, p, c);
                    if (s > 0) tsum += t;        // one-hot: sum>0 <=> any set
                    else       t00 = t;          // background slot (q==0,k==0)
                } else {                          // box slots 81..84 (q==3)
                    float d  = p - t;
                    float ad = fabsf(d);
                    sl += (ad < 1.0f) ? 0.5f * d * d : (ad - 0.5f);
                }
            }
        }

        // width-4 segmented reduction (2 levels)
        #pragma unroll
        for (int off = 2; off; off >>= 1) {
            c    += __shfl_down_sync(0xffffffffu, c,    off, 4);
            sl   += __shfl_down_sync(0xffffffffu, sl,   off, 4);
            tsum += __shfl_down_sync(0xffffffffu, tsum, off, 4);
        }

        if (q == 0 && a < valid) {
            float conf = -c;
            if (tsum != 0.0f) { accN++; accPos += conf; accLoc += sl; }
            if (t00 != 0.0f) {                   // negative (background) anchor
                int bin = (int)((conf - HIST_LO) * HIST_INVW);
                bin = max(0, min(NBINS - 1, bin));
                atomicAdd(&s_cnt[bin], 1);
                atomicAdd(&s_sum[bin], conf);
            }
        }
    }

    if (q == 0 && accN) {
        atomicAdd(&g_npos, accN);
        atomicAdd(&g_pos_loss, (double)accPos);
        atomicAdd(&g_loc_loss, (double)accLoc);
    }

    __syncthreads();
    for (int i = tid; i < NBINS; i += 256) {
        int cc = s_cnt[i];
        if (cc) {
            atomicAdd(&g_hist_cnt[i], cc);
            atomicAdd(&g_hist_sum[i], s_sum[i]);
        }
    }
}

// ---------------- K2: single-block finalize ----------------
__global__ __launch_bounds__(1024) void ssd_finalize_kernel(float* __restrict__ out)
{
    __shared__ int    s_cnt[NBINS];
    __shared__ float  s_sumf[NBINS];
    __shared__ int    s_chunk[1024];
    __shared__ double s_neg;

    const int tid = threadIdx.x;
    for (int i = tid; i < NBINS; i += 1024) {
        int b = NBINS - 1 - i;          // rank from the top value downward
        s_cnt[i]  = g_hist_cnt[b];
        s_sumf[i] = g_hist_sum[b];
    }
    if (tid == 0) s_neg = 0.0;
    __syncthreads();

    int c0 = s_cnt[tid * 3 + 0];
    int c1 = s_cnt[tid * 3 + 1];
    int c2 = s_cnt[tid * 3 + 2];
    int total = c0 + c1 + c2;

    // inclusive Hillis-Steele scan of per-thread chunk totals
    s_chunk[tid] = total;
    __syncthreads();
    for (int off = 1; off < 1024; off <<= 1) {
        int v = (tid >= off) ? s_chunk[tid - off] : 0;
        __syncthreads();
        s_chunk[tid] += v;
        __syncthreads();
    }
    int cumBefore = s_chunk[tid] - total;

    int npos = g_npos;
    int nneg = (int)(3.0f * (float)npos);

    double contrib = 0.0;
    int cb = cumBefore;
    int cnts[3] = {c0, c1, c2};
    #pragma unroll
    for (int k = 0; k < 3; k++) {
        int cc = cnts[k];
        if (cc) {
            float s = s_sumf[tid * 3 + k];
            if (cb + cc <= nneg) {
                contrib += (double)s;                                    // fully taken
            } else if (cb < nneg) {
                contrib += (double)s * (double)(nneg - cb) / (double)cc; // straddling bin
            }
        }
        cb += cc;
    }
    if (contrib != 0.0) atomicAdd(&s_neg, contrib);
    __syncthreads();

    if (tid == 0) {
        double np = (npos > 0) ? (double)npos : 1.0;
        out[0] = (float)((g_pos_loss + s_neg + g_loc_loss) / np);
    }
}

// ---------------- entry point ----------------
extern "C" void kernel_launch(void* const* d_in, const int* in_sizes, int n_in,
                              void* d_out, int out_size)
{
    const float* y_pred = (const float*)d_in[0];
    const float* y_true = (const float*)d_in[1];
    float* out = (float*)d_out;

    int nanch = in_sizes[0] / SLOTS;

    // smem: 2 staging arrays + histogram (counts + sums)
    const size_t smem_bytes = (size_t)2 * TILE_F * sizeof(float)
                            + (size_t)NBINS * (sizeof(int) + sizeof(float));
    static bool attr_done = false;
    if (!attr_done) {
        cudaFuncSetAttribute(ssd_main_kernel,
                             cudaFuncAttributeMaxDynamicSharedMemorySize,
                             (int)smem_bytes);
        attr_done = true;
    }

    ssd_init_kernel<<<(NBINS + 255) / 256, 256>>>();
    ssd_main_kernel<<<NBLOCKS, 256, smem_bytes>>>(y_pred, y_true, nanch);
    ssd_finalize_kernel<<<1, 1024>>>(out);
}

// round 4
// speedup vs baseline: 1.7601x; 1.7601x over previous
#include <cuda_runtime.h>
#include <math.h>

// ---------------- problem constants ----------------
#define SLOTS      85      // 81 classes + 4 box coords
#define NBINS      4096
#define HIST_LO   (-8.0f)
#define HIST_INVW (256.0f)   // NBINS / 16
#define NBLOCKS    888       // 6 per SM

// ---------------- device scratch ----------------
__device__ int    g_npos;
__device__ double g_pos_loss;
__device__ double g_loc_loss;
__device__ int    g_hist_cnt[NBINS];
__device__ float  g_hist_sum[NBINS];

// ---------------- K0: zero scratch ----------------
__global__ void ssd_init_kernel() {
    int i = blockIdx.x * blockDim.x + threadIdx.x;
    if (i < NBINS) { g_hist_cnt[i] = 0; g_hist_sum[i] = 0.0f; }
    if (i == 0) { g_npos = 0; g_pos_loss = 0.0; g_loc_loss = 0.0; }
}

// ---------------- K1: one-hot gather pass, warp per anchor, 2x unroll ----
// y_true class rows are one-hot, so conf = -y_pred[hot_idx]. We stream only
// y_true (coalesced) and gather a single y_pred float per anchor (+ 4 box
// floats for the ~2% positive anchors, predicated).
__global__ __launch_bounds__(256) void ssd_main_kernel(
    const float* __restrict__ yp,
    const float* __restrict__ yt,
    int nanch)
{
    __shared__ int   s_cnt[NBINS];
    __shared__ float s_sum[NBINS];
    for (int i = threadIdx.x; i < NBINS; i += blockDim.x) { s_cnt[i] = 0; s_sum[i] = 0.0f; }
    __syncthreads();

    const int lane = threadIdx.x & 31;
    const int warp = threadIdx.x >> 5;

    long long wid    = (long long)blockIdx.x * 8 + warp;
    long long nwarps = (long long)NBLOCKS * 8;

    float accLoc = 0.0f;                 // per-lane smooth-L1 accumulator
    float accPos = 0.0f;                 // lane-0 accumulators
    int   accN   = 0;

    for (long long a0 = wid * 2; a0 < nanch; a0 += nwarps * 2) {
        const long long aB = a0 + 1;
        const bool  bv = (aB < nanch);
        const size_t rA = (size_t)a0 * SLOTS;
        const size_t rB = (size_t)aB * SLOTS;

        // ---- stream y_true rows (all loads independent -> high MLP) ----
        float ta0 = yt[rA + lane];
        float ta1 = yt[rA + lane + 32];
        float ta2 = (lane < 21) ? yt[rA + lane + 64] : 0.0f;
        float tb0 = 0.0f, tb1 = 0.0f, tb2 = 0.0f;
        if (bv) {
            tb0 = yt[rB + lane];
            tb1 = yt[rB + lane + 32];
            tb2 = (lane < 21) ? yt[rB + lane + 64] : 0.0f;
        }

        // ---- hot class index per anchor (exactly one slot is nonzero) ----
        int la = -1;
        if (ta0 != 0.0f) la = lane;
        if (ta1 != 0.0f) la = lane + 32;
        if (lane < 17 && ta2 != 0.0f) la = lane + 64;
        int lb = -1;
        if (tb0 != 0.0f) lb = lane;
        if (tb1 != 0.0f) lb = lane + 32;
        if (lane < 17 && tb2 != 0.0f) lb = lane + 64;

        int hotA = __reduce_max_sync(0xffffffffu, la);
        int hotB = __reduce_max_sync(0xffffffffu, lb);

        const bool posA = (hotA > 0);
        const bool posB = bv && (hotB > 0);

        // ---- gather the single needed y_pred class value (lane 0) ----
        float confA = 0.0f, confB = 0.0f;
        if (lane == 0) {
            confA = -yp[rA + max(hotA, 0)];
            if (bv) confB = -yp[rB + max(hotB, 0)];
        }

        // ---- smooth-L1 on box slots (lanes 17..20), positives only ----
        if (lane >= 17 && lane < 21) {
            if (posA) {
                float d  = yp[rA + lane + 64] - ta2;
                float ad = fabsf(d);
                accLoc += (ad < 1.0f) ? 0.5f * d * d : (ad - 0.5f);
            }
            if (posB) {
                float d  = yp[rB + lane + 64] - tb2;
                float ad = fabsf(d);
                accLoc += (ad < 1.0f) ? 0.5f * d * d : (ad - 0.5f);
            }
        }

        // ---- per-anchor bookkeeping on lane 0 ----
        if (lane == 0) {
            if (posA) { accN++; accPos += confA; }
            else if (hotA == 0) {
                int bin = (int)((confA - HIST_LO) * HIST_INVW);
                bin = max(0, min(NBINS - 1, bin));
                atomicAdd(&s_cnt[bin], 1);
                atomicAdd(&s_sum[bin], confA);
            }
            if (bv) {
                if (posB) { accN++; accPos += confB; }
                else if (hotB == 0) {
                    int bin = (int)((confB - HIST_LO) * HIST_INVW);
                    bin = max(0, min(NBINS - 1, bin));
                    atomicAdd(&s_cnt[bin], 1);
                    atomicAdd(&s_sum[bin], confB);
                }
            }
        }
    }

    // ---- flush: reduce accLoc within warp, then one global atomic per warp
    #pragma unroll
    for (int off = 16; off; off >>= 1)
        accLoc += __shfl_down_sync(0xffffffffu, accLoc, off);

    if (lane == 0) {
        if (accLoc != 0.0f) atomicAdd(&g_loc_loss, (double)accLoc);
        if (accN) {
            atomicAdd(&g_npos, accN);
            atomicAdd(&g_pos_loss, (double)accPos);
        }
    }

    __syncthreads();
    for (int i = threadIdx.x; i < NBINS; i += blockDim.x) {
        int cc = s_cnt[i];
        if (cc) {
            atomicAdd(&g_hist_cnt[i], cc);
            atomicAdd(&g_hist_sum[i], s_sum[i]);
        }
    }
}

// ---------------- K2: single-block finalize ----------------
__global__ __launch_bounds__(1024) void ssd_finalize_kernel(float* __restrict__ out)
{
    __shared__ int    s_cnt[NBINS];
    __shared__ float  s_sumf[NBINS];
    __shared__ int    s_chunk[1024];
    __shared__ double s_neg;

    const int tid = threadIdx.x;
    for (int i = tid; i < NBINS; i += 1024) {
        int b = NBINS - 1 - i;          // rank from the top value downward
        s_cnt[i]  = g_hist_cnt[b];
        s_sumf[i] = g_hist_sum[b];
    }
    if (tid == 0) s_neg = 0.0;
    __syncthreads();

    int c0 = s_cnt[tid * 4 + 0];
    int c1 = s_cnt[tid * 4 + 1];
    int c2 = s_cnt[tid * 4 + 2];
    int c3 = s_cnt[tid * 4 + 3];
    int total = c0 + c1 + c2 + c3;

    // inclusive Hillis-Steele scan of per-thread chunk totals
    s_chunk[tid] = total;
    __syncthreads();
    for (int off = 1; off < 1024; off <<= 1) {
        int v = (tid >= off) ? s_chunk[tid - off] : 0;
        __syncthreads();
        s_chunk[tid] += v;
        __syncthreads();
    }
    int cumBefore = s_chunk[tid] - total;   // negatives strictly above this chunk

    int npos = g_npos;
    int nneg = (int)(3.0f * (float)npos);

    double contrib = 0.0;
    int cb = cumBefore;
    int cnts[4] = {c0, c1, c2, c3};
    #pragma unroll
    for (int k = 0; k < 4; k++) {
        int cc = cnts[k];
        if (cc) {
            float s = s_sumf[tid * 4 + k];
            if (cb + cc <= nneg) {
                contrib += (double)s;                                    // fully taken
            } else if (cb < nneg) {
                contrib += (double)s * (double)(nneg - cb) / (double)cc; // straddling bin
            }
        }
        cb += cc;
    }
    if (contrib != 0.0) atomicAdd(&s_neg, contrib);
    __syncthreads();

    if (tid == 0) {
        double np = (npos > 0) ? (double)npos : 1.0;
        out[0] = (float)((g_pos_loss + s_neg + g_loc_loss) / np);
    }
}

// ---------------- entry point ----------------
extern "C" void kernel_launch(void* const* d_in, const int* in_sizes, int n_in,
                              void* d_out, int out_size)
{
    const float* y_pred = (const float*)d_in[0];
    const float* y_true = (const float*)d_in[1];
    float* out = (float*)d_out;

    int nanch = in_sizes[0] / SLOTS;

    ssd_init_kernel<<<(NBINS + 255) / 256, 256>>>();
    ssd_main_kernel<<<NBLOCKS, 256>>>(y_pred, y_true, nanch);
    ssd_finalize_kernel<<<1, 1024>>>(out);
}

// round 5
// speedup vs baseline: 2.2816x; 1.2963x over previous
#include <cuda_runtime.h>
#include <math.h>

// ---------------- problem constants ----------------
#define SLOTS      85      // 81 classes + 4 box coords
#define NBINS      4096
#define HIST_LO   (-8.0f)
#define HIST_INVW (256.0f)   // NBINS / 16
#define NBLOCKS    888       // 6 per SM

// ---------------- device scratch (statically zero-initialized; finalize
// kernel re-zeroes it at the end of every replay) ----------------
__device__ int    g_npos;
__device__ double g_pos_loss;
__device__ double g_loc_loss;
__device__ int    g_hist_cnt[NBINS];
__device__ float  g_hist_sum[NBINS];

// ---------------- K1: one-hot gather pass, warp = 4 anchors ----------------
// y_true class rows are one-hot: conf = -y_pred[hot]. Background value
// y_pred[r+0] is loaded UP FRONT (independent of the reduction) since 98% of
// anchors are negatives (hot==0); only positives pay a dependent gather.
__global__ __launch_bounds__(256) void ssd_main_kernel(
    const float* __restrict__ yp,
    const float* __restrict__ yt,
    int nanch)
{
    __shared__ int   s_cnt[NBINS];
    __shared__ float s_sum[NBINS];
    for (int i = threadIdx.x; i < NBINS; i += 256) { s_cnt[i] = 0; s_sum[i] = 0.0f; }
    __syncthreads();

    const int lane = threadIdx.x & 31;
    const int warp = threadIdx.x >> 5;

    const long long wid    = (long long)blockIdx.x * 8 + warp;
    const long long stride = (long long)NBLOCKS * 8 * 4;   // anchors per grid step

    float accPos = 0.0f, accLoc = 0.0f;
    int   accN = 0;

    for (long long a0 = wid * 4; a0 < nanch; a0 += stride) {
        // validity + row bases
        bool   v0 = true,                v1 = (a0 + 1 < nanch);
        bool   v2 = (a0 + 2 < nanch),    v3 = (a0 + 3 < nanch);
        size_t r0 = (size_t)(a0    ) * SLOTS;
        size_t r1 = (size_t)(a0 + 1) * SLOTS;
        size_t r2 = (size_t)(a0 + 2) * SLOTS;
        size_t r3 = (size_t)(a0 + 3) * SLOTS;

        // ---- front-batched independent loads (12 yt + 1 yp-bg) ----
        float t0a = yt[r0 + lane];
        float t0b = yt[r0 + lane + 32];
        float t0c = (lane < 17) ? yt[r0 + lane + 64] : 0.0f;
        float t1a = v1 ? yt[r1 + lane]       : 0.0f;
        float t1b = v1 ? yt[r1 + lane + 32]  : 0.0f;
        float t1c = (v1 && lane < 17) ? yt[r1 + lane + 64] : 0.0f;
        float t2a = v2 ? yt[r2 + lane]       : 0.0f;
        float t2b = v2 ? yt[r2 + lane + 32]  : 0.0f;
        float t2c = (v2 && lane < 17) ? yt[r2 + lane + 64] : 0.0f;
        float t3a = v3 ? yt[r3 + lane]       : 0.0f;
        float t3b = v3 ? yt[r3 + lane + 32]  : 0.0f;
        float t3c = (v3 && lane < 17) ? yt[r3 + lane + 64] : 0.0f;

        // background logits: lane i<4 loads yp[(a0+i)*SLOTS]
        float bg = 0.0f;
        if (lane < 4 && a0 + lane < nanch)
            bg = yp[(size_t)(a0 + lane) * SLOTS];

        // ---- hot class index per anchor (exactly one class slot nonzero) ----
        int la0 = -1, la1 = -1, la2 = -1, la3 = -1;
        if (t0a != 0.0f) la0 = lane;
        if (t0b != 0.0f) la0 = lane + 32;
        if (t0c != 0.0f) la0 = lane + 64;
        if (t1a != 0.0f) la1 = lane;
        if (t1b != 0.0f) la1 = lane + 32;
        if (t1c != 0.0f) la1 = lane + 64;
        if (t2a != 0.0f) la2 = lane;
        if (t2b != 0.0f) la2 = lane + 32;
        if (t2c != 0.0f) la2 = lane + 64;
        if (t3a != 0.0f) la3 = lane;
        if (t3b != 0.0f) la3 = lane + 32;
        if (t3c != 0.0f) la3 = lane + 64;

        int hot0 = __reduce_max_sync(0xffffffffu, la0);
        int hot1 = __reduce_max_sync(0xffffffffu, la1);
        int hot2 = __reduce_max_sync(0xffffffffu, la2);
        int hot3 = __reduce_max_sync(0xffffffffu, la3);

        // ---- per-anchor bookkeeping: lane i (0..3) owns anchor i ----
        if (lane < 4) {
            int    h  = hot0;
            size_t r  = r0;
            bool   v  = v0;
            if (lane == 1) { h = hot1; r = r1; v = v1; }
            if (lane == 2) { h = hot2; r = r2; v = v2; }
            if (lane == 3) { h = hot3; r = r3; v = v3; }

            if (v) {
                if (h > 0) {                         // positive (~2%): gather
                    float conf = -yp[r + h];
                    accN++; accPos += conf;
                } else {                              // negative: bg preloaded
                    float conf = -bg;
                    int bin = (int)((conf - HIST_LO) * HIST_INVW);
                    bin = max(0, min(NBINS - 1, bin));
                    atomicAdd(&s_cnt[bin], 1);
                    atomicAdd(&s_sum[bin], conf);
                }
            }
        }

        // ---- box smooth-L1: lanes 16..31, anchor j = (lane-16)>>2, coord = lane&3
        if (lane >= 16) {
            int j = (lane - 16) >> 2;
            int coord = lane & 3;
            int    h = hot0;  size_t r = r0;  bool v = v0;
            if (j == 1) { h = hot1; r = r1; v = v1; }
            if (j == 2) { h = hot2; r = r2; v = v2; }
            if (j == 3) { h = hot3; r = r3; v = v3; }
            if (v && h > 0) {                        // positives only (~2%)
                size_t rb = r + 81 + coord;
                float d  = yp[rb] - yt[rb];
                float ad = fabsf(d);
                accLoc += (ad < 1.0f) ? 0.5f * d * d : (ad - 0.5f);
            }
        }
    }

    // ---- warp flush: reduce scattered accumulators, one atomic set per warp
    #pragma unroll
    for (int off = 16; off; off >>= 1) {
        accPos += __shfl_down_sync(0xffffffffu, accPos, off);
        accLoc += __shfl_down_sync(0xffffffffu, accLoc, off);
    }
    int warpN = __reduce_add_sync(0xffffffffu, accN);

    if (lane == 0) {
        if (warpN) {
            atomicAdd(&g_npos, warpN);
            atomicAdd(&g_pos_loss, (double)accPos);
        }
        if (accLoc != 0.0f) atomicAdd(&g_loc_loss, (double)accLoc);
    }

    __syncthreads();
    for (int i = threadIdx.x; i < NBINS; i += 256) {
        int cc = s_cnt[i];
        if (cc) {
            atomicAdd(&g_hist_cnt[i], cc);
            atomicAdd(&g_hist_sum[i], s_sum[i]);
        }
    }
}

// ---------------- K2: single-block finalize (+ re-zero scratch) ----------------
__global__ __launch_bounds__(1024) void ssd_finalize_kernel(float* __restrict__ out)
{
    __shared__ int    s_cnt[NBINS];
    __shared__ float  s_sumf[NBINS];
    __shared__ int    s_chunk[1024];
    __shared__ double s_neg;

    const int tid = threadIdx.x;
    for (int i = tid; i < NBINS; i += 1024) {
        int b = NBINS - 1 - i;          // rank from the top value downward
        s_cnt[i]  = g_hist_cnt[b];
        s_sumf[i] = g_hist_sum[b];
    }
    if (tid == 0) s_neg = 0.0;
    __syncthreads();

    int c0 = s_cnt[tid * 4 + 0];
    int c1 = s_cnt[tid * 4 + 1];
    int c2 = s_cnt[tid * 4 + 2];
    int c3 = s_cnt[tid * 4 + 3];
    int total = c0 + c1 + c2 + c3;

    // inclusive Hillis-Steele scan of per-thread chunk totals
    s_chunk[tid] = total;
    __syncthreads();
    for (int off = 1; off < 1024; off <<= 1) {
        int v = (tid >= off) ? s_chunk[tid - off] : 0;
        __syncthreads();
        s_chunk[tid] += v;
        __syncthreads();
    }
    int cumBefore = s_chunk[tid] - total;

    int npos = g_npos;
    int nneg = (int)(3.0f * (float)npos);

    double contrib = 0.0;
    int cb = cumBefore;
    int cnts[4] = {c0, c1, c2, c3};
    #pragma unroll
    for (int k = 0; k < 4; k++) {
        int cc = cnts[k];
        if (cc) {
            float s = s_sumf[tid * 4 + k];
            if (cb + cc <= nneg) {
                contrib += (double)s;                                    // fully taken
            } else if (cb < nneg) {
                contrib += (double)s * (double)(nneg - cb) / (double)cc; // straddling bin
            }
        }
        cb += cc;
    }
    if (contrib != 0.0) atomicAdd(&s_neg, contrib);
    __syncthreads();

    if (tid == 0) {
        double np = (npos > 0) ? (double)npos : 1.0;
        out[0] = (float)((g_pos_loss + s_neg + g_loc_loss) / np);
    }

    // ---- re-zero scratch so the next graph replay starts clean ----
    __syncthreads();
    for (int i = tid; i < NBINS; i += 1024) {
        g_hist_cnt[i] = 0;
        g_hist_sum[i] = 0.0f;
    }
    if (tid == 0) { g_npos = 0; g_pos_loss = 0.0; g_loc_loss = 0.0; }
}

// ---------------- entry point ----------------
extern "C" void kernel_launch(void* const* d_in, const int* in_sizes, int n_in,
                              void* d_out, int out_size)
{
    const float* y_pred = (const float*)d_in[0];
    const float* y_true = (const float*)d_in[1];
    float* out = (float*)d_out;

    int nanch = in_sizes[0] / SLOTS;

    ssd_main_kernel<<<NBLOCKS, 256>>>(y_pred, y_true, nanch);
    ssd_finalize_kernel<<<1, 1024>>>(out);
}